// round 15
// baseline (speedup 1.0000x reference)
#include <cuda_runtime.h>
#include <cuda_bf16.h>
#include <stdint.h>
#include <math.h>

#define B_   4
#define C_   256
#define HW_  4096
#define G_   32
#define CPG_ 8
#define CD_  512
#define NTOK (B_*HW_)

// scale folded into Q columns of qkv output: (1/16) * log2(e)
#define QSCALE_F 0.0901650905f

// ---------------------------------------------------------------------------
// Scratch (device globals)
// ---------------------------------------------------------------------------
__device__ float g_sb[B_ * 2 * C_];
__device__ float g_mean[B_ * G_];
__device__ float g_rinv[B_ * G_];
__device__ __nv_bfloat16 g_t[NTOK * C_];
__device__ __nv_bfloat16 g_qkv[NTOK * 3 * C_];
__device__ __nv_bfloat16 g_o[NTOK * C_];
__device__ __nv_bfloat16 g_wq[3 * C_ * C_];
__device__ __nv_bfloat16 g_wp[C_ * C_];

// ---------------------------------------------------------------------------
// PTX helpers
// ---------------------------------------------------------------------------
__device__ __forceinline__ uint32_t smem_u32(const void* p) {
    uint32_t a;
    asm("{ .reg .u64 t; cvta.to.shared.u64 t, %1; cvt.u32.u64 %0, t; }" : "=r"(a) : "l"(p));
    return a;
}
__device__ __forceinline__ void cp16(uint32_t dst, const void* src) {
    asm volatile("cp.async.cg.shared.global [%0], [%1], 16;" :: "r"(dst), "l"(src));
}
#define CP_COMMIT() asm volatile("cp.async.commit_group;" ::: "memory")
#define CP_WAIT(n)  asm volatile("cp.async.wait_group %0;" :: "n"(n) : "memory")

__device__ __forceinline__ void ldsm4(uint32_t& r0, uint32_t& r1, uint32_t& r2, uint32_t& r3,
                                      uint32_t addr) {
    asm volatile("ldmatrix.sync.aligned.m8n8.x4.shared.b16 {%0,%1,%2,%3}, [%4];"
                 : "=r"(r0), "=r"(r1), "=r"(r2), "=r"(r3) : "r"(addr));
}
__device__ __forceinline__ void ldsm4t(uint32_t& r0, uint32_t& r1, uint32_t& r2, uint32_t& r3,
                                       uint32_t addr) {
    asm volatile("ldmatrix.sync.aligned.m8n8.x4.trans.shared.b16 {%0,%1,%2,%3}, [%4];"
                 : "=r"(r0), "=r"(r1), "=r"(r2), "=r"(r3) : "r"(addr));
}
__device__ __forceinline__ void mma_bf16(float c[4],
                                         uint32_t a0, uint32_t a1, uint32_t a2, uint32_t a3,
                                         uint32_t b0, uint32_t b1) {
    asm volatile(
        "mma.sync.aligned.m16n8k16.row.col.f32.bf16.bf16.f32 "
        "{%0,%1,%2,%3},{%4,%5,%6,%7},{%8,%9},{%0,%1,%2,%3};\n"
        : "+f"(c[0]), "+f"(c[1]), "+f"(c[2]), "+f"(c[3])
        : "r"(a0), "r"(a1), "r"(a2), "r"(a3), "r"(b0), "r"(b1));
}
__device__ __forceinline__ uint32_t packbf(float a, float b) {
    __nv_bfloat162 h = __floats2bfloat162_rn(a, b);
    return *(uint32_t*)&h;
}

// ---------------------------------------------------------------------------
// Fused flash attention — 512 threads, 16 warps, 128 Q rows, 64-key blocks.
//   Phase 1 (QK): warp (rowblk=w>>1, kh=w&1) computes S[16 rows][32 keys],
//                 stores bf16 S to smem (row stride 72 halves).
//   Phase 2 (PV): warp (rowblk, ch=w&1) ldsm-reads S[16][64], softmax,
//                 accumulates O over column half ch (o_ = 64 regs).
// ---------------------------------------------------------------------------
#define FLDK 264
#define LDS_S 72
#define FQ_BYTES  (128 * FLDK * 2)                 // 67584
#define FKV_BYTES (64 * FLDK * 2)                  // 33792
#define FK_OFF(s) (FQ_BYTES + (s) * FKV_BYTES)
#define FV_OFF(s) (FQ_BYTES + 2 * FKV_BYTES + (s) * FKV_BYTES)
#define FS_OFF    (FQ_BYTES + 4 * FKV_BYTES)       // 202752
#define FSM_TOT   (FS_OFF + 128 * LDS_S * 2)       // 221184

__global__ void __launch_bounds__(512, 1)
flash_attn(const __nv_bfloat16* __restrict__ qkv, __nv_bfloat16* __restrict__ O) {
    extern __shared__ char smraw[];
    const uint32_t sb = smem_u32(smraw);
    const int b = blockIdx.y;
    const int m0 = blockIdx.x * 128;
    const int tid = threadIdx.x;
    const int lane = tid & 31, warp = tid >> 5;
    const int rowblk = warp >> 1;        // 0..7
    const int wh = warp & 1;             // key-half (phase 1) / col-half (phase 2)
    const __nv_bfloat16* base = qkv + (size_t)b * HW_ * 768;

    {   // Q prologue: 128 rows x 32 chunks(16B); thread -> (row = tid/4, 8 chunks)
        const int qr = tid >> 2, qc = (tid & 3) * 8;
        const __nv_bfloat16* src = base + (size_t)(m0 + qr) * 768;
        #pragma unroll
        for (int i = 0; i < 8; i++)
            cp16(sb + (qr * FLDK + (qc + i) * 8) * 2, src + (qc + i) * 8);
    }
    // K/V loader: 64 rows x 32 chunks each; thread -> (row = tid/8, 4 chunks)
    const int kr = tid >> 3, kc = (tid & 7) * 4;
    auto load_kv = [&](int st, int j) {
        const __nv_bfloat16* srck = base + (size_t)(j * 64 + kr) * 768 + 256;
        const __nv_bfloat16* srcv = srck + 256;
        const uint32_t dk = sb + FK_OFF(st) + (kr * FLDK) * 2;
        const uint32_t dv = sb + FV_OFF(st) + (kr * FLDK) * 2;
        #pragma unroll
        for (int i = 0; i < 4; i++) cp16(dk + (kc + i) * 16, srck + (kc + i) * 8);
        #pragma unroll
        for (int i = 0; i < 4; i++) cp16(dv + (kc + i) * 16, srcv + (kc + i) * 8);
    };
    load_kv(0, 0);
    CP_COMMIT();
    load_kv(1, 1);
    CP_COMMIT();

    const int lr16 = lane & 15, lc2 = lane >> 4;
    const int fr = lane >> 2, fc = (lane & 3) * 2;
    const uint32_t q_lm = sb + ((rowblk * 16 + lr16) * FLDK + lc2 * 8) * 2;
    const uint32_t s_lm = sb + FS_OFF + ((rowblk * 16 + lr16) * LDS_S + lc2 * 8) * 2;
    char* const s_wr_base = smraw + FS_OFF;

    float o_[16][4];
    #pragma unroll
    for (int i = 0; i < 16; i++)
        #pragma unroll
        for (int j = 0; j < 4; j++) o_[i][j] = 0.f;
    float m0r = -1e30f, m1r = -1e30f, l0r = 0.f, l1r = 0.f;

    for (int j = 0; j < 64; j++) {
        if (j == 63) { CP_WAIT(0); } else { CP_WAIT(1); }
        __syncthreads();
        const int st = j & 1;

        // ================= Phase 1: S = Q' K^T (16 rows x 32 keys) =========
        {
            const uint32_t k_lm = sb + FK_OFF(st) +
                                  ((wh * 32 + lr16) * FLDK + lc2 * 8) * 2;
            float s_[4][4];
            #pragma unroll
            for (int i = 0; i < 4; i++)
                #pragma unroll
                for (int c = 0; c < 4; c++) s_[i][c] = 0.f;
            #pragma unroll
            for (int ks = 0; ks < 16; ks++) {
                uint32_t a0, a1, a2, a3;
                ldsm4(a0, a1, a2, a3, q_lm + ks * 32);
                #pragma unroll
                for (int np = 0; np < 2; np++) {
                    uint32_t r0, r1, r2, r3;
                    ldsm4(r0, r1, r2, r3, k_lm + np * 16 * FLDK * 2 + ks * 32);
                    mma_bf16(s_[2 * np],     a0, a1, a2, a3, r0, r2);
                    mma_bf16(s_[2 * np + 1], a0, a1, a2, a3, r1, r3);
                }
            }
            // store bf16 S tile: rows rowblk*16 + fr(+8), cols wh*32 + i*8 + fc
            const int r0w = rowblk * 16 + fr;
            #pragma unroll
            for (int i = 0; i < 4; i++) {
                const int col = wh * 32 + i * 8 + fc;
                *(uint32_t*)(s_wr_base + (r0w * LDS_S + col) * 2)       = packbf(s_[i][0], s_[i][1]);
                *(uint32_t*)(s_wr_base + ((r0w + 8) * LDS_S + col) * 2) = packbf(s_[i][2], s_[i][3]);
            }
        }
        __syncthreads();

        // ================= Phase 2: softmax + O += P V (col half wh) =======
        {
            // read S[16 rows][64 keys] as 4 k16 A-fragments
            uint32_t sv[4][4];
            #pragma unroll
            for (int kt = 0; kt < 4; kt++)
                ldsm4(sv[kt][0], sv[kt][1], sv[kt][2], sv[kt][3], s_lm + kt * 32);

            // block max per row half (bf16 pair-max, then unpack once)
            __nv_bfloat162 vm0 = *(__nv_bfloat162*)&sv[0][0];
            __nv_bfloat162 vm1 = *(__nv_bfloat162*)&sv[0][1];
            vm0 = __hmax2(vm0, *(__nv_bfloat162*)&sv[0][2]);
            vm1 = __hmax2(vm1, *(__nv_bfloat162*)&sv[0][3]);
            #pragma unroll
            for (int kt = 1; kt < 4; kt++) {
                vm0 = __hmax2(vm0, *(__nv_bfloat162*)&sv[kt][0]);
                vm0 = __hmax2(vm0, *(__nv_bfloat162*)&sv[kt][2]);
                vm1 = __hmax2(vm1, *(__nv_bfloat162*)&sv[kt][1]);
                vm1 = __hmax2(vm1, *(__nv_bfloat162*)&sv[kt][3]);
            }
            float bm0 = fmaxf(__bfloat162float(vm0.x), __bfloat162float(vm0.y));
            float bm1 = fmaxf(__bfloat162float(vm1.x), __bfloat162float(vm1.y));
            bm0 = fmaxf(bm0, __shfl_xor_sync(0xffffffffu, bm0, 1));
            bm0 = fmaxf(bm0, __shfl_xor_sync(0xffffffffu, bm0, 2));
            bm1 = fmaxf(bm1, __shfl_xor_sync(0xffffffffu, bm1, 1));
            bm1 = fmaxf(bm1, __shfl_xor_sync(0xffffffffu, bm1, 2));
            const float pm0 = m0r, pm1 = m1r;
            const float mn0 = fmaxf(pm0, bm0), mn1 = fmaxf(pm1, bm1);
            m0r = mn0; m1r = mn1;

            if (mn0 != pm0 || mn1 != pm1) {
                const float sc0 = exp2f(pm0 - mn0), sc1 = exp2f(pm1 - mn1);
                l0r *= sc0; l1r *= sc1;
                #pragma unroll
                for (int i = 0; i < 16; i++) {
                    o_[i][0] *= sc0; o_[i][1] *= sc0;
                    o_[i][2] *= sc1; o_[i][3] *= sc1;
                }
            }

            // exp + repack to A-fragments
            uint32_t pbk[4][4];
            float ls0 = 0.f, ls1 = 0.f;
            #pragma unroll
            for (int kt = 0; kt < 4; kt++) {
                #pragma unroll
                for (int r = 0; r < 4; r++) {
                    const __nv_bfloat162 sp = *(__nv_bfloat162*)&sv[kt][r];
                    const float mref = (r & 1) ? mn1 : mn0;
                    float p0 = exp2f(__bfloat162float(sp.x) - mref);
                    float p1 = exp2f(__bfloat162float(sp.y) - mref);
                    if (r & 1) ls1 += p0 + p1; else ls0 += p0 + p1;
                    pbk[kt][r] = packbf(p0, p1);
                }
            }
            l0r += ls0;
            l1r += ls1;

            // O += P V  (cols wh*128 .. +128)
            const uint32_t v_lm = sb + FV_OFF(st) +
                                  (lr16 * FLDK + wh * 128 + lc2 * 8) * 2;
            #pragma unroll
            for (int kt = 0; kt < 4; kt++) {
                const uint32_t a0 = pbk[kt][0], a1 = pbk[kt][1];
                const uint32_t a2 = pbk[kt][2], a3 = pbk[kt][3];
                #pragma unroll
                for (int np = 0; np < 8; np++) {
                    uint32_t r0, r1, r2, r3;
                    ldsm4t(r0, r1, r2, r3, v_lm + kt * 16 * FLDK * 2 + np * 32);
                    mma_bf16(o_[2 * np],     a0, a1, a2, a3, r0, r1);
                    mma_bf16(o_[2 * np + 1], a0, a1, a2, a3, r2, r3);
                }
            }
        }
        __syncthreads();
        if (j + 2 < 64) { load_kv(st, j + 2); CP_COMMIT(); }
    }

    // ---- epilogue ----
    l0r += __shfl_xor_sync(0xffffffffu, l0r, 1);
    l0r += __shfl_xor_sync(0xffffffffu, l0r, 2);
    l1r += __shfl_xor_sync(0xffffffffu, l1r, 1);
    l1r += __shfl_xor_sync(0xffffffffu, l1r, 2);
    const float inv0 = 1.f / l0r, inv1 = 1.f / l1r;
    const int row0 = m0 + rowblk * 16 + fr;
    __nv_bfloat16* op0 = O + ((size_t)b * HW_ + row0) * C_ + wh * 128;
    __nv_bfloat16* op1 = op0 + 8 * C_;
    #pragma unroll
    for (int nt = 0; nt < 16; nt++) {
        const int col = nt * 8 + fc;
        *(__nv_bfloat162*)&op0[col] = __floats2bfloat162_rn(o_[nt][0] * inv0, o_[nt][1] * inv0);
        *(__nv_bfloat162*)&op1[col] = __floats2bfloat162_rn(o_[nt][2] * inv1, o_[nt][3] * inv1);
    }
}

// ---------------------------------------------------------------------------
// bf16 NT GEMM (R10): QSC scales cols<256; RES fuses residual+transpose
// ---------------------------------------------------------------------------
#define LDK 72
#define ASZ (128 * LDK * 2)
#define STG (2 * ASZ)
#define GSM (2 * STG)

template <bool HASBIAS, bool QSC, bool RES>
__global__ void __launch_bounds__(256)
gemm_nt_bf16(const __nv_bfloat16* __restrict__ A, int lda, size_t sA,
             const __nv_bfloat16* __restrict__ Bm, int ldb, size_t sB,
             __nv_bfloat16* __restrict__ Cm, int ldc, size_t sC,
             int K, const float* __restrict__ bias,
             const float* __restrict__ xres, float* __restrict__ outf) {
    extern __shared__ char smraw[];
    const uint32_t sb = smem_u32(smraw);
    const int bz = blockIdx.z;
    A  += (size_t)bz * sA;
    Bm += (size_t)bz * sB;
    Cm += (size_t)bz * sC;
    const int m0 = blockIdx.y * 128, n0 = blockIdx.x * 128;
    const int tid = threadIdx.x;
    const int lane = tid & 31, warp = tid >> 5;
    const int wm = (warp & 3) * 32, wn = (warp >> 2) * 64;

    const int lrow = tid >> 1, lcol = (tid & 1) * 4;
    const __nv_bfloat16* aptr = A  + (size_t)(m0 + lrow) * lda + lcol * 8;
    const __nv_bfloat16* bptr = Bm + (size_t)(n0 + lrow) * ldb + lcol * 8;
    const uint32_t sa_st = sb + lrow * 144 + lcol * 16;
    const uint32_t sb_st = sb + ASZ + lrow * 144 + lcol * 16;
    const int NT = K / 64;

    #pragma unroll
    for (int s = 0; s < 2; s++) {
        const int k0 = s * 64;
        #pragma unroll
        for (int j = 0; j < 4; j++) {
            cp16(sa_st + s * STG + j * 16, aptr + k0 + j * 8);
            cp16(sb_st + s * STG + j * 16, bptr + k0 + j * 8);
        }
        CP_COMMIT();
    }

    const int lr16 = lane & 15, lc2 = lane >> 4;
    const uint32_t a_lm = sb + ((wm + lr16) * LDK + lc2 * 8) * 2;
    const uint32_t b_lm = sb + ASZ + ((wn + lr16) * LDK + lc2 * 8) * 2;

    float acc[2][8][4] = {};
    for (int kt = 0; kt < NT; kt++) {
        const int st = kt & 1;
        if (kt == NT - 1) { CP_WAIT(0); } else { CP_WAIT(1); }
        __syncthreads();
        const uint32_t a_base = a_lm + st * STG;
        const uint32_t b_base = b_lm + st * STG;
        #pragma unroll
        for (int ks = 0; ks < 4; ks++) {
            uint32_t af[2][4], bq[4][4];
            ldsm4(af[0][0], af[0][1], af[0][2], af[0][3], a_base + ks * 32);
            ldsm4(af[1][0], af[1][1], af[1][2], af[1][3], a_base + 16 * LDK * 2 + ks * 32);
            #pragma unroll
            for (int c = 0; c < 4; c++)
                ldsm4(bq[c][0], bq[c][1], bq[c][2], bq[c][3],
                      b_base + c * 16 * LDK * 2 + ks * 32);
            #pragma unroll
            for (int mt = 0; mt < 2; mt++)
                #pragma unroll
                for (int nt = 0; nt < 8; nt++) {
                    const int cch = nt >> 1, w = nt & 1;
                    mma_bf16(acc[mt][nt], af[mt][0], af[mt][1], af[mt][2], af[mt][3],
                             bq[cch][w], bq[cch][w + 2]);
                }
        }
        __syncthreads();
        if (kt + 2 < NT) {
            const int k0 = (kt + 2) * 64;
            #pragma unroll
            for (int j = 0; j < 4; j++) {
                cp16(sa_st + st * STG + j * 16, aptr + k0 + j * 8);
                cp16(sb_st + st * STG + j * 16, bptr + k0 + j * 8);
            }
            CP_COMMIT();
        }
    }

    const int fr = lane >> 2, fc = (lane & 3) * 2;
    if (!RES) {
        #pragma unroll
        for (int mt = 0; mt < 2; mt++)
            #pragma unroll
            for (int nt = 0; nt < 8; nt++) {
                const int gn = n0 + wn + nt * 8 + fc;
                float b0 = 0.f, b1 = 0.f;
                if (HASBIAS) { b0 = bias[gn]; b1 = bias[gn + 1]; }
                float cs = 1.f;
                if (QSC) cs = (gn < C_) ? QSCALE_F : 1.f;
                #pragma unroll
                for (int rr = 0; rr < 2; rr++) {
                    const int gm = m0 + wm + mt * 16 + fr + rr * 8;
                    float v0 = (acc[mt][nt][rr * 2 + 0] + b0) * cs;
                    float v1 = (acc[mt][nt][rr * 2 + 1] + b1) * cs;
                    *(__nv_bfloat162*)&Cm[(size_t)gm * ldc + gn] = __floats2bfloat162_rn(v0, v1);
                }
            }
    } else {
        float* tf = (float*)smraw;                         // 128 x 132 floats
        #pragma unroll
        for (int mt = 0; mt < 2; mt++)
            #pragma unroll
            for (int nt = 0; nt < 8; nt++) {
                const int cl = wn + nt * 8 + fc;
                float b0 = 0.f, b1 = 0.f;
                if (HASBIAS) { b0 = bias[n0 + cl]; b1 = bias[n0 + cl + 1]; }
                #pragma unroll
                for (int rr = 0; rr < 2; rr++) {
                    const int ml = wm + mt * 16 + fr + rr * 8;
                    tf[ml * 132 + cl]     = acc[mt][nt][rr * 2 + 0] + b0;
                    tf[ml * 132 + cl + 1] = acc[mt][nt][rr * 2 + 1] + b1;
                }
            }
        __syncthreads();
        const int bb = m0 >> 12;
        const int nr = m0 & (HW_ - 1);
        const int nb = lane * 4;
        #pragma unroll
        for (int pass = 0; pass < 16; pass++) {
            const int ch = pass * 8 + warp;
            float4 v;
            v.x = tf[(nb + 0) * 132 + ch];
            v.y = tf[(nb + 1) * 132 + ch];
            v.z = tf[(nb + 2) * 132 + ch];
            v.w = tf[(nb + 3) * 132 + ch];
            const size_t idx = ((size_t)bb * C_ + n0 + ch) * HW_ + nr + nb;
            const float4 xv = *(const float4*)&xres[idx];
            v.x += xv.x; v.y += xv.y; v.z += xv.z; v.w += xv.w;
            *(float4*)&outf[idx] = v;
        }
    }
}

// ---------------------------------------------------------------------------
// Merged prep kernel: cond_linear (8) | gn_stats (128) | wt qkv (192) | wt proj (64)
// ---------------------------------------------------------------------------
#define PREP_SHM 1056

__global__ void __launch_bounds__(256)
prep_kernel(const float* __restrict__ cond, const float* __restrict__ lin_w,
            const float* __restrict__ lin_b, float* __restrict__ sb,
            const float* __restrict__ x, float* __restrict__ mean,
            float* __restrict__ rinv,
            const float* __restrict__ qkv_w, __nv_bfloat16* __restrict__ wq,
            const float* __restrict__ proj_w, __nv_bfloat16* __restrict__ wp) {
    __shared__ float shm[PREP_SHM];
    const int bid = blockIdx.x;
    const int tid = threadIdx.x;

    if (bid < 8) {
        const int b = bid >> 1;
        for (int k = tid; k < CD_; k += 256) shm[k] = cond[b * CD_ + k];
        __syncthreads();
        const int j = (bid & 1) * 256 + tid;
        float acc = lin_b[j];
        #pragma unroll 8
        for (int k = 0; k < CD_; k++) acc += shm[k] * lin_w[k * (2 * C_) + j];
        sb[b * (2 * C_) + j] = acc;
    } else if (bid < 136) {
        const int bg = bid - 8;
        const float* p = x + (size_t)bg * CPG_ * HW_;
        float s = 0.f, ss = 0.f;
        for (int i = tid; i < CPG_ * HW_; i += 256) {
            float v = p[i];
            s += v; ss += v * v;
        }
        #pragma unroll
        for (int o = 16; o > 0; o >>= 1) {
            s  += __shfl_xor_sync(0xffffffffu, s,  o);
            ss += __shfl_xor_sync(0xffffffffu, ss, o);
        }
        if ((tid & 31) == 0) { shm[tid >> 5] = s; shm[32 + (tid >> 5)] = ss; }
        __syncthreads();
        if (tid == 0) {
            s = 0.f; ss = 0.f;
            #pragma unroll
            for (int i = 0; i < 8; i++) { s += shm[i]; ss += shm[32 + i]; }
            float m = s * (1.f / (CPG_ * HW_));
            float var = ss * (1.f / (CPG_ * HW_)) - m * m;
            mean[bg] = m;
            rinv[bg] = rsqrtf(var + 1e-5f);
        }
    } else {
        const float* w;
        __nv_bfloat16* wt;
        int N, idx;
        if (bid < 328) { idx = bid - 136; w = qkv_w; wt = wq; N = 3 * C_; }
        else           { idx = bid - 328; w = proj_w; wt = wp; N = C_; }
        const int nblk = N / 32;
        const int n0 = (idx % nblk) * 32, k0 = (idx / nblk) * 32;
        float (*tile)[33] = (float(*)[33])shm;
        const int ty = tid >> 5, tx = tid & 31;
        #pragma unroll
        for (int i = ty; i < 32; i += 8)
            tile[i][tx] = w[(size_t)(k0 + i) * N + n0 + tx];
        __syncthreads();
        #pragma unroll
        for (int i = ty; i < 32; i += 8)
            wt[(size_t)(n0 + i) * C_ + k0 + tx] = __float2bfloat16(tile[tx][i]);
    }
}

// ---------------------------------------------------------------------------
// GN apply + affine + transpose -> t [B,HW,C] bf16
// ---------------------------------------------------------------------------
__global__ void __launch_bounds__(256)
gn_apply_t_kernel(const float* __restrict__ x,
                  const float* __restrict__ sb,
                  const float* __restrict__ mean,
                  const float* __restrict__ rinv,
                  __nv_bfloat16* __restrict__ t) {
    __shared__ float tile[32][133];
    const int b = blockIdx.z;
    const int c0 = blockIdx.y * 32, n0 = blockIdx.x * 128;
    const int tid = threadIdx.x;

    const int nl = (tid & 31) * 4;
    #pragma unroll
    for (int pass = 0; pass < 4; pass++) {
        const int cl = pass * 8 + (tid >> 5);
        const int c = c0 + cl;
        const int g = b * G_ + (c >> 3);
        const float m = mean[g], r = rinv[g];
        const float sc = 1.f + sb[b * 2 * C_ + c];
        const float bi = sb[b * 2 * C_ + C_ + c];
        const float4 v = *(const float4*)&x[((size_t)b * C_ + c) * HW_ + n0 + nl];
        tile[cl][nl + 0] = (v.x - m) * r * sc + bi;
        tile[cl][nl + 1] = (v.y - m) * r * sc + bi;
        tile[cl][nl + 2] = (v.z - m) * r * sc + bi;
        tile[cl][nl + 3] = (v.w - m) * r * sc + bi;
    }
    __syncthreads();
    const int q = tid & 15;
    #pragma unroll
    for (int pass = 0; pass < 8; pass++) {
        const int no = pass * 16 + (tid >> 4);
        __nv_bfloat162 pk = __floats2bfloat162_rn(tile[2 * q][no], tile[2 * q + 1][no]);
        *(__nv_bfloat162*)&t[((size_t)b * HW_ + n0 + no) * C_ + c0 + 2 * q] = pk;
    }
}

// ---------------------------------------------------------------------------
// Host launcher (5 kernels)
// ---------------------------------------------------------------------------
extern "C" void kernel_launch(void* const* d_in, const int* in_sizes, int n_in,
                              void* d_out, int out_size) {
    const float* x      = (const float*)d_in[0];
    const float* cond   = (const float*)d_in[1];
    const float* lin_w  = (const float*)d_in[2];
    const float* lin_b  = (const float*)d_in[3];
    const float* qkv_w  = (const float*)d_in[4];
    const float* qkv_b  = (const float*)d_in[5];
    const float* proj_w = (const float*)d_in[6];
    const float* proj_b = (const float*)d_in[7];
    float* out = (float*)d_out;

    float *sb, *mean, *rinv;
    __nv_bfloat16 *t, *qkv, *o, *wq, *wp;
    cudaGetSymbolAddress((void**)&sb,   g_sb);
    cudaGetSymbolAddress((void**)&mean, g_mean);
    cudaGetSymbolAddress((void**)&rinv, g_rinv);
    cudaGetSymbolAddress((void**)&t,    g_t);
    cudaGetSymbolAddress((void**)&qkv,  g_qkv);
    cudaGetSymbolAddress((void**)&o,    g_o);
    cudaGetSymbolAddress((void**)&wq,   g_wq);
    cudaGetSymbolAddress((void**)&wp,   g_wp);

    cudaFuncSetAttribute((const void*)gemm_nt_bf16<true, true, false>,
                         cudaFuncAttributeMaxDynamicSharedMemorySize, GSM);
    cudaFuncSetAttribute((const void*)gemm_nt_bf16<true, false, true>,
                         cudaFuncAttributeMaxDynamicSharedMemorySize, GSM);
    cudaFuncSetAttribute((const void*)flash_attn,
                         cudaFuncAttributeMaxDynamicSharedMemorySize, FSM_TOT);

    // 1: prep
    prep_kernel<<<392, 256>>>(cond, lin_w, lin_b, sb, x, mean, rinv,
                              qkv_w, wq, proj_w, wp);

    // 2: GN apply + transpose -> tokens
    gn_apply_t_kernel<<<dim3(HW_ / 128, C_ / 32, B_), 256>>>(x, sb, mean, rinv, t);

    // 3: qkv = t @ wq^T + b   (Q cols pre-scaled by 1/16*log2e)
    gemm_nt_bf16<true, true, false><<<dim3(3 * C_ / 128, NTOK / 128, 1), 256, GSM>>>(
        t, C_, 0, wq, C_, 0, qkv, 3 * C_, 0, C_, qkv_b, nullptr, nullptr);

    // 4: fused flash attention (512 thr, split-K/split-N warps)
    flash_attn<<<dim3(HW_ / 128, B_), 512, FSM_TOT>>>(qkv, o);

    // 5: proj + residual + transpose, fused
    gemm_nt_bf16<true, false, true><<<dim3(C_ / 128, NTOK / 128, 1), 256, GSM>>>(
        o, C_, 0, wp, C_, 0, nullptr, C_, 0, C_, proj_b, x, out);
}

// round 16
// speedup vs baseline: 1.0342x; 1.0342x over previous
#include <cuda_runtime.h>
#include <cuda_bf16.h>
#include <stdint.h>
#include <math.h>

#define B_   4
#define C_   256
#define HW_  4096
#define G_   32
#define CPG_ 8
#define CD_  512
#define NTOK (B_*HW_)

// scale folded into Q columns of qkv output: (1/16) * log2(e)
#define QSCALE_F 0.0901650905f

// ---------------------------------------------------------------------------
// Scratch (device globals)
// ---------------------------------------------------------------------------
__device__ float g_sb[B_ * 2 * C_];
__device__ float g_mean[B_ * G_];
__device__ float g_rinv[B_ * G_];
__device__ __nv_bfloat16 g_qkv[NTOK * 3 * C_];
__device__ __nv_bfloat16 g_o[NTOK * C_];
__device__ __nv_bfloat16 g_wq[3 * C_ * C_];
__device__ __nv_bfloat16 g_wp[C_ * C_];

// ---------------------------------------------------------------------------
// PTX helpers
// ---------------------------------------------------------------------------
__device__ __forceinline__ uint32_t smem_u32(const void* p) {
    uint32_t a;
    asm("{ .reg .u64 t; cvta.to.shared.u64 t, %1; cvt.u32.u64 %0, t; }" : "=r"(a) : "l"(p));
    return a;
}
__device__ __forceinline__ void cp16(uint32_t dst, const void* src) {
    asm volatile("cp.async.cg.shared.global [%0], [%1], 16;" :: "r"(dst), "l"(src));
}
#define CP_COMMIT() asm volatile("cp.async.commit_group;" ::: "memory")
#define CP_WAIT(n)  asm volatile("cp.async.wait_group %0;" :: "n"(n) : "memory")

__device__ __forceinline__ void ldsm4(uint32_t& r0, uint32_t& r1, uint32_t& r2, uint32_t& r3,
                                      uint32_t addr) {
    asm volatile("ldmatrix.sync.aligned.m8n8.x4.shared.b16 {%0,%1,%2,%3}, [%4];"
                 : "=r"(r0), "=r"(r1), "=r"(r2), "=r"(r3) : "r"(addr));
}
__device__ __forceinline__ void ldsm4t(uint32_t& r0, uint32_t& r1, uint32_t& r2, uint32_t& r3,
                                       uint32_t addr) {
    asm volatile("ldmatrix.sync.aligned.m8n8.x4.trans.shared.b16 {%0,%1,%2,%3}, [%4];"
                 : "=r"(r0), "=r"(r1), "=r"(r2), "=r"(r3) : "r"(addr));
}
__device__ __forceinline__ void mma_bf16(float c[4],
                                         uint32_t a0, uint32_t a1, uint32_t a2, uint32_t a3,
                                         uint32_t b0, uint32_t b1) {
    asm volatile(
        "mma.sync.aligned.m16n8k16.row.col.f32.bf16.bf16.f32 "
        "{%0,%1,%2,%3},{%4,%5,%6,%7},{%8,%9},{%0,%1,%2,%3};\n"
        : "+f"(c[0]), "+f"(c[1]), "+f"(c[2]), "+f"(c[3])
        : "r"(a0), "r"(a1), "r"(a2), "r"(a3), "r"(b0), "r"(b1));
}
__device__ __forceinline__ uint32_t packbf(float a, float b) {
    __nv_bfloat162 h = __floats2bfloat162_rn(a, b);
    return *(uint32_t*)&h;
}

// ---------------------------------------------------------------------------
// Fused flash attention (R14 config: 256 thr, 128 Q rows, 64-key blocks)
// ---------------------------------------------------------------------------
#define FLDK 264
#define FQ_BYTES (128 * FLDK * 2)
#define FK_BYTES (64 * FLDK * 2)
#define FK_OFF(s) (FQ_BYTES + (s) * FK_BYTES)
#define FV_OFF(s) (FQ_BYTES + 2 * FK_BYTES + (s) * FK_BYTES)
#define FSM_TOT  (FQ_BYTES + 4 * FK_BYTES)

__global__ void __launch_bounds__(256, 1)
flash_attn(const __nv_bfloat16* __restrict__ qkv, __nv_bfloat16* __restrict__ O) {
    extern __shared__ char smraw[];
    const uint32_t sb = smem_u32(smraw);
    const int b = blockIdx.y;
    const int m0 = blockIdx.x * 128;
    const int tid = threadIdx.x;
    const int lane = tid & 31, warp = tid >> 5;
    const __nv_bfloat16* base = qkv + (size_t)b * HW_ * 768;

    {   // Q prologue
        const int qr = tid >> 1, qc = (tid & 1) * 16;
        const __nv_bfloat16* src = base + (size_t)(m0 + qr) * 768 + qc * 8;
        const uint32_t dst = sb + (qr * FLDK + qc * 8) * 2;
        #pragma unroll
        for (int i = 0; i < 16; i++) cp16(dst + i * 16, src + i * 8);
    }
    const int kr = tid >> 2, kc = (tid & 3) * 8;
    auto load_kv = [&](int st, int j) {
        const __nv_bfloat16* srck = base + (size_t)(j * 64 + kr) * 768 + 256 + kc * 8;
        const __nv_bfloat16* srcv = srck + 256;
        const uint32_t dk = sb + FK_OFF(st) + (kr * FLDK + kc * 8) * 2;
        const uint32_t dv = sb + FV_OFF(st) + (kr * FLDK + kc * 8) * 2;
        #pragma unroll
        for (int i = 0; i < 8; i++) { cp16(dk + i * 16, srck + i * 8); }
        #pragma unroll
        for (int i = 0; i < 8; i++) { cp16(dv + i * 16, srcv + i * 8); }
    };
    load_kv(0, 0);
    CP_COMMIT();
    load_kv(1, 1);
    CP_COMMIT();

    const int lr16 = lane & 15, lc2 = lane >> 4;
    const uint32_t q_lm = sb + ((warp * 16 + lr16) * FLDK + lc2 * 8) * 2;

    float o_[32][4];
    #pragma unroll
    for (int i = 0; i < 32; i++)
        #pragma unroll
        for (int j = 0; j < 4; j++) o_[i][j] = 0.f;
    float m0r = -1e30f, m1r = -1e30f, l0r = 0.f, l1r = 0.f;

    for (int j = 0; j < 64; j++) {
        if (j == 63) { CP_WAIT(0); } else { CP_WAIT(1); }
        __syncthreads();
        const int st = j & 1;
        const uint32_t k_lm = sb + FK_OFF(st) + (lr16 * FLDK + lc2 * 8) * 2;
        const uint32_t v_lm = sb + FV_OFF(st) + (lr16 * FLDK + lc2 * 8) * 2;

        // ---- S = Q' K^T (already log2-scaled) ----
        float s_[8][4];
        #pragma unroll
        for (int i = 0; i < 8; i++)
            #pragma unroll
            for (int c = 0; c < 4; c++) s_[i][c] = 0.f;
        #pragma unroll
        for (int ks = 0; ks < 16; ks++) {
            uint32_t a0, a1, a2, a3;
            ldsm4(a0, a1, a2, a3, q_lm + ks * 32);
            #pragma unroll
            for (int np = 0; np < 4; np++) {
                uint32_t r0, r1, r2, r3;
                ldsm4(r0, r1, r2, r3, k_lm + np * 16 * FLDK * 2 + ks * 32);
                mma_bf16(s_[2 * np],     a0, a1, a2, a3, r0, r2);
                mma_bf16(s_[2 * np + 1], a0, a1, a2, a3, r1, r3);
            }
        }

        // ---- online softmax (base 2) ----
        float bm0 = -1e30f, bm1 = -1e30f;
        #pragma unroll
        for (int i = 0; i < 8; i++) {
            bm0 = fmaxf(bm0, fmaxf(s_[i][0], s_[i][1]));
            bm1 = fmaxf(bm1, fmaxf(s_[i][2], s_[i][3]));
        }
        bm0 = fmaxf(bm0, __shfl_xor_sync(0xffffffffu, bm0, 1));
        bm0 = fmaxf(bm0, __shfl_xor_sync(0xffffffffu, bm0, 2));
        bm1 = fmaxf(bm1, __shfl_xor_sync(0xffffffffu, bm1, 1));
        bm1 = fmaxf(bm1, __shfl_xor_sync(0xffffffffu, bm1, 2));
        const float pm0 = m0r, pm1 = m1r;
        const float mn0 = fmaxf(pm0, bm0), mn1 = fmaxf(pm1, bm1);
        m0r = mn0; m1r = mn1;

        if (mn0 != pm0 || mn1 != pm1) {
            const float sc0 = exp2f(pm0 - mn0), sc1 = exp2f(pm1 - mn1);
            l0r *= sc0; l1r *= sc1;
            #pragma unroll
            for (int i = 0; i < 32; i++) {
                o_[i][0] *= sc0; o_[i][1] *= sc0;
                o_[i][2] *= sc1; o_[i][3] *= sc1;
            }
        }

        uint32_t pb[8][2];
        float ls0 = 0.f, ls1 = 0.f;
        #pragma unroll
        for (int i = 0; i < 8; i++) {
            float p00 = exp2f(s_[i][0] - mn0);
            float p01 = exp2f(s_[i][1] - mn0);
            float p10 = exp2f(s_[i][2] - mn1);
            float p11 = exp2f(s_[i][3] - mn1);
            ls0 += p00 + p01; ls1 += p10 + p11;
            pb[i][0] = packbf(p00, p01);
            pb[i][1] = packbf(p10, p11);
        }
        l0r += ls0;
        l1r += ls1;

        // ---- O += P V ----
        #pragma unroll
        for (int kk = 0; kk < 4; kk++) {
            const uint32_t a0 = pb[2 * kk][0], a1 = pb[2 * kk][1];
            const uint32_t a2 = pb[2 * kk + 1][0], a3 = pb[2 * kk + 1][1];
            #pragma unroll
            for (int np = 0; np < 16; np++) {
                uint32_t r0, r1, r2, r3;
                ldsm4t(r0, r1, r2, r3, v_lm + kk * 16 * FLDK * 2 + np * 32);
                mma_bf16(o_[2 * np],     a0, a1, a2, a3, r0, r1);
                mma_bf16(o_[2 * np + 1], a0, a1, a2, a3, r2, r3);
            }
        }
        __syncthreads();
        if (j + 2 < 64) { load_kv(st, j + 2); CP_COMMIT(); }
    }

    // ---- epilogue ----
    l0r += __shfl_xor_sync(0xffffffffu, l0r, 1);
    l0r += __shfl_xor_sync(0xffffffffu, l0r, 2);
    l1r += __shfl_xor_sync(0xffffffffu, l1r, 1);
    l1r += __shfl_xor_sync(0xffffffffu, l1r, 2);
    const float inv0 = 1.f / l0r, inv1 = 1.f / l1r;
    const int row0 = m0 + warp * 16 + (lane >> 2);
    const int colb = (lane & 3) * 2;
    __nv_bfloat16* op0 = O + ((size_t)b * HW_ + row0) * C_;
    __nv_bfloat16* op1 = op0 + 8 * C_;
    #pragma unroll
    for (int nt = 0; nt < 32; nt++) {
        const int col = nt * 8 + colb;
        *(__nv_bfloat162*)&op0[col] = __floats2bfloat162_rn(o_[nt][0] * inv0, o_[nt][1] * inv0);
        *(__nv_bfloat162*)&op1[col] = __floats2bfloat162_rn(o_[nt][2] * inv1, o_[nt][3] * inv1);
    }
}

// ---------------------------------------------------------------------------
// bf16 NT GEMM:
//   GNA: A operand produced on the fly = GN-normalized x (fp32 -> bf16)
//   QSC: scale output cols<256 by QSCALE_F
//   RES: fused residual epilogue (transpose + x + fp32 out)
// ---------------------------------------------------------------------------
#define LDK 72
#define ASZ (128 * LDK * 2)
#define STG (2 * ASZ)
#define GSM (2 * STG)

template <bool HASBIAS, bool QSC, bool RES, bool GNA>
__global__ void __launch_bounds__(256)
gemm_nt_bf16(const __nv_bfloat16* __restrict__ A, int lda, size_t sA,
             const __nv_bfloat16* __restrict__ Bm, int ldb, size_t sB,
             __nv_bfloat16* __restrict__ Cm, int ldc, size_t sC,
             int K, const float* __restrict__ bias,
             const float* __restrict__ xres, float* __restrict__ outf,
             const float* __restrict__ gmean, const float* __restrict__ grinv,
             const float* __restrict__ gsb) {
    extern __shared__ char smraw[];
    const uint32_t sb = smem_u32(smraw);
    const int bz = blockIdx.z;
    A  += (size_t)bz * sA;
    Bm += (size_t)bz * sB;
    Cm += (size_t)bz * sC;
    const int m0 = blockIdx.y * 128, n0 = blockIdx.x * 128;
    const int tid = threadIdx.x;
    const int lane = tid & 31, warp = tid >> 5;
    const int wm = (warp & 3) * 32, wn = (warp >> 2) * 64;

    const int lrow = tid >> 1, lcol = (tid & 1) * 4;
    const __nv_bfloat16* aptr = A  + (size_t)(m0 + lrow) * lda + lcol * 8;
    const __nv_bfloat16* bptr = Bm + (size_t)(n0 + lrow) * ldb + lcol * 8;
    const uint32_t sa_st = sb + lrow * 144 + lcol * 16;
    const uint32_t sb_st = sb + ASZ + lrow * 144 + lcol * 16;
    const int NT = K / 64;

    // --- GNA coords: channel pair + token group ---
    const int gcp = tid >> 3;            // 0..31 channel pair
    const int gtq = tid & 7;             // token group of 16
    const int gbb = m0 >> 12;            // batch (128 | 4096)
    const int gn0 = m0 & (HW_ - 1);
    auto load_a_gn = [&](int stg, int kt) {
        const int ch0 = kt * 64 + 2 * gcp;
        const int gg = gbb * G_ + (ch0 >> 3);
        const float gm = gmean[gg], gr = grinv[gg];
        const float s0 = 1.f + gsb[gbb * 2 * C_ + ch0];
        const float b0v = gsb[gbb * 2 * C_ + C_ + ch0];
        const float s1 = 1.f + gsb[gbb * 2 * C_ + ch0 + 1];
        const float b1v = gsb[gbb * 2 * C_ + C_ + ch0 + 1];
        const float* x0 = xres + ((size_t)gbb * C_ + ch0) * HW_ + gn0 + gtq * 16;
        const float* x1 = x0 + HW_;
        char* dst = smraw + stg * STG;
        #pragma unroll
        for (int i = 0; i < 4; i++) {
            const float4 v0 = *(const float4*)(x0 + i * 4);
            const float4 v1 = *(const float4*)(x1 + i * 4);
            const int t0 = gtq * 16 + i * 4;
            *(uint32_t*)(dst + ((t0 + 0) * LDK + 2 * gcp) * 2) =
                packbf((v0.x - gm) * gr * s0 + b0v, (v1.x - gm) * gr * s1 + b1v);
            *(uint32_t*)(dst + ((t0 + 1) * LDK + 2 * gcp) * 2) =
                packbf((v0.y - gm) * gr * s0 + b0v, (v1.y - gm) * gr * s1 + b1v);
            *(uint32_t*)(dst + ((t0 + 2) * LDK + 2 * gcp) * 2) =
                packbf((v0.z - gm) * gr * s0 + b0v, (v1.z - gm) * gr * s1 + b1v);
            *(uint32_t*)(dst + ((t0 + 3) * LDK + 2 * gcp) * 2) =
                packbf((v0.w - gm) * gr * s0 + b0v, (v1.w - gm) * gr * s1 + b1v);
        }
    };

    #pragma unroll
    for (int s = 0; s < 2; s++) {
        const int k0 = s * 64;
        if (GNA) {
            load_a_gn(s, s);
        } else {
            #pragma unroll
            for (int j = 0; j < 4; j++)
                cp16(sa_st + s * STG + j * 16, aptr + k0 + j * 8);
        }
        #pragma unroll
        for (int j = 0; j < 4; j++)
            cp16(sb_st + s * STG + j * 16, bptr + k0 + j * 8);
        CP_COMMIT();
    }

    const int lr16 = lane & 15, lc2 = lane >> 4;
    const uint32_t a_lm = sb + ((wm + lr16) * LDK + lc2 * 8) * 2;
    const uint32_t b_lm = sb + ASZ + ((wn + lr16) * LDK + lc2 * 8) * 2;

    float acc[2][8][4] = {};
    for (int kt = 0; kt < NT; kt++) {
        const int st = kt & 1;
        if (kt == NT - 1) { CP_WAIT(0); } else { CP_WAIT(1); }
        __syncthreads();
        const uint32_t a_base = a_lm + st * STG;
        const uint32_t b_base = b_lm + st * STG;
        #pragma unroll
        for (int ks = 0; ks < 4; ks++) {
            uint32_t af[2][4], bq[4][4];
            ldsm4(af[0][0], af[0][1], af[0][2], af[0][3], a_base + ks * 32);
            ldsm4(af[1][0], af[1][1], af[1][2], af[1][3], a_base + 16 * LDK * 2 + ks * 32);
            #pragma unroll
            for (int c = 0; c < 4; c++)
                ldsm4(bq[c][0], bq[c][1], bq[c][2], bq[c][3],
                      b_base + c * 16 * LDK * 2 + ks * 32);
            #pragma unroll
            for (int mt = 0; mt < 2; mt++)
                #pragma unroll
                for (int nt = 0; nt < 8; nt++) {
                    const int cch = nt >> 1, w = nt & 1;
                    mma_bf16(acc[mt][nt], af[mt][0], af[mt][1], af[mt][2], af[mt][3],
                             bq[cch][w], bq[cch][w + 2]);
                }
        }
        __syncthreads();
        if (kt + 2 < NT) {
            const int k0 = (kt + 2) * 64;
            if (GNA) {
                load_a_gn(st, kt + 2);
            } else {
                #pragma unroll
                for (int j = 0; j < 4; j++)
                    cp16(sa_st + st * STG + j * 16, aptr + k0 + j * 8);
            }
            #pragma unroll
            for (int j = 0; j < 4; j++)
                cp16(sb_st + st * STG + j * 16, bptr + k0 + j * 8);
            CP_COMMIT();
        }
    }

    const int fr = lane >> 2, fc = (lane & 3) * 2;
    if (!RES) {
        #pragma unroll
        for (int mt = 0; mt < 2; mt++)
            #pragma unroll
            for (int nt = 0; nt < 8; nt++) {
                const int gn = n0 + wn + nt * 8 + fc;
                float b0 = 0.f, b1 = 0.f;
                if (HASBIAS) { b0 = bias[gn]; b1 = bias[gn + 1]; }
                float cs = 1.f;
                if (QSC) cs = (gn < C_) ? QSCALE_F : 1.f;
                #pragma unroll
                for (int rr = 0; rr < 2; rr++) {
                    const int gm = m0 + wm + mt * 16 + fr + rr * 8;
                    float v0 = (acc[mt][nt][rr * 2 + 0] + b0) * cs;
                    float v1 = (acc[mt][nt][rr * 2 + 1] + b1) * cs;
                    *(__nv_bfloat162*)&Cm[(size_t)gm * ldc + gn] = __floats2bfloat162_rn(v0, v1);
                }
            }
    } else {
        float* tf = (float*)smraw;                         // 128 x 132 floats
        #pragma unroll
        for (int mt = 0; mt < 2; mt++)
            #pragma unroll
            for (int nt = 0; nt < 8; nt++) {
                const int cl = wn + nt * 8 + fc;
                float b0 = 0.f, b1 = 0.f;
                if (HASBIAS) { b0 = bias[n0 + cl]; b1 = bias[n0 + cl + 1]; }
                #pragma unroll
                for (int rr = 0; rr < 2; rr++) {
                    const int ml = wm + mt * 16 + fr + rr * 8;
                    tf[ml * 132 + cl]     = acc[mt][nt][rr * 2 + 0] + b0;
                    tf[ml * 132 + cl + 1] = acc[mt][nt][rr * 2 + 1] + b1;
                }
            }
        __syncthreads();
        const int bb = m0 >> 12;
        const int nr = m0 & (HW_ - 1);
        const int nb = lane * 4;
        #pragma unroll
        for (int pass = 0; pass < 16; pass++) {
            const int ch = pass * 8 + warp;
            float4 v;
            v.x = tf[(nb + 0) * 132 + ch];
            v.y = tf[(nb + 1) * 132 + ch];
            v.z = tf[(nb + 2) * 132 + ch];
            v.w = tf[(nb + 3) * 132 + ch];
            const size_t idx = ((size_t)bb * C_ + n0 + ch) * HW_ + nr + nb;
            const float4 xv = *(const float4*)&xres[idx];
            v.x += xv.x; v.y += xv.y; v.z += xv.z; v.w += xv.w;
            *(float4*)&outf[idx] = v;
        }
    }
}

// ---------------------------------------------------------------------------
// Merged prep kernel: cond_linear (8) | gn_stats (128) | wt qkv (192) | wt proj (64)
// ---------------------------------------------------------------------------
#define PREP_SHM 1056

__global__ void __launch_bounds__(256)
prep_kernel(const float* __restrict__ cond, const float* __restrict__ lin_w,
            const float* __restrict__ lin_b, float* __restrict__ sb,
            const float* __restrict__ x, float* __restrict__ mean,
            float* __restrict__ rinv,
            const float* __restrict__ qkv_w, __nv_bfloat16* __restrict__ wq,
            const float* __restrict__ proj_w, __nv_bfloat16* __restrict__ wp) {
    __shared__ float shm[PREP_SHM];
    const int bid = blockIdx.x;
    const int tid = threadIdx.x;

    if (bid < 8) {
        const int b = bid >> 1;
        for (int k = tid; k < CD_; k += 256) shm[k] = cond[b * CD_ + k];
        __syncthreads();
        const int j = (bid & 1) * 256 + tid;
        float acc = lin_b[j];
        #pragma unroll 8
        for (int k = 0; k < CD_; k++) acc += shm[k] * lin_w[k * (2 * C_) + j];
        sb[b * (2 * C_) + j] = acc;
    } else if (bid < 136) {
        const int bg = bid - 8;
        const float* p = x + (size_t)bg * CPG_ * HW_;
        float s = 0.f, ss = 0.f;
        for (int i = tid; i < CPG_ * HW_; i += 256) {
            float v = p[i];
            s += v; ss += v * v;
        }
        #pragma unroll
        for (int o = 16; o > 0; o >>= 1) {
            s  += __shfl_xor_sync(0xffffffffu, s,  o);
            ss += __shfl_xor_sync(0xffffffffu, ss, o);
        }
        if ((tid & 31) == 0) { shm[tid >> 5] = s; shm[32 + (tid >> 5)] = ss; }
        __syncthreads();
        if (tid == 0) {
            s = 0.f; ss = 0.f;
            #pragma unroll
            for (int i = 0; i < 8; i++) { s += shm[i]; ss += shm[32 + i]; }
            float m = s * (1.f / (CPG_ * HW_));
            float var = ss * (1.f / (CPG_ * HW_)) - m * m;
            mean[bg] = m;
            rinv[bg] = rsqrtf(var + 1e-5f);
        }
    } else {
        const float* w;
        __nv_bfloat16* wt;
        int N, idx;
        if (bid < 328) { idx = bid - 136; w = qkv_w; wt = wq; N = 3 * C_; }
        else           { idx = bid - 328; w = proj_w; wt = wp; N = C_; }
        const int nblk = N / 32;
        const int n0 = (idx % nblk) * 32, k0 = (idx / nblk) * 32;
        float (*tile)[33] = (float(*)[33])shm;
        const int ty = tid >> 5, tx = tid & 31;
        #pragma unroll
        for (int i = ty; i < 32; i += 8)
            tile[i][tx] = w[(size_t)(k0 + i) * N + n0 + tx];
        __syncthreads();
        #pragma unroll
        for (int i = ty; i < 32; i += 8)
            wt[(size_t)(n0 + i) * C_ + k0 + tx] = __float2bfloat16(tile[tx][i]);
    }
}

// ---------------------------------------------------------------------------
// Host launcher (4 kernels)
// ---------------------------------------------------------------------------
extern "C" void kernel_launch(void* const* d_in, const int* in_sizes, int n_in,
                              void* d_out, int out_size) {
    const float* x      = (const float*)d_in[0];
    const float* cond   = (const float*)d_in[1];
    const float* lin_w  = (const float*)d_in[2];
    const float* lin_b  = (const float*)d_in[3];
    const float* qkv_w  = (const float*)d_in[4];
    const float* qkv_b  = (const float*)d_in[5];
    const float* proj_w = (const float*)d_in[6];
    const float* proj_b = (const float*)d_in[7];
    float* out = (float*)d_out;

    float *sb, *mean, *rinv;
    __nv_bfloat16 *qkv, *o, *wq, *wp;
    cudaGetSymbolAddress((void**)&sb,   g_sb);
    cudaGetSymbolAddress((void**)&mean, g_mean);
    cudaGetSymbolAddress((void**)&rinv, g_rinv);
    cudaGetSymbolAddress((void**)&qkv,  g_qkv);
    cudaGetSymbolAddress((void**)&o,    g_o);
    cudaGetSymbolAddress((void**)&wq,   g_wq);
    cudaGetSymbolAddress((void**)&wp,   g_wp);

    cudaFuncSetAttribute((const void*)gemm_nt_bf16<true, true, false, true>,
                         cudaFuncAttributeMaxDynamicSharedMemorySize, GSM);
    cudaFuncSetAttribute((const void*)gemm_nt_bf16<true, false, true, false>,
                         cudaFuncAttributeMaxDynamicSharedMemorySize, GSM);
    cudaFuncSetAttribute((const void*)flash_attn,
                         cudaFuncAttributeMaxDynamicSharedMemorySize, FSM_TOT);

    // 1: prep (cond linear | gn stats | weight transposes)
    prep_kernel<<<392, 256>>>(cond, lin_w, lin_b, sb, x, mean, rinv,
                              qkv_w, wq, proj_w, wp);

    // 2: qkv = GN(x) @ wq^T + b   (GN fused into A loader; Q cols pre-scaled)
    gemm_nt_bf16<true, true, false, true><<<dim3(3 * C_ / 128, NTOK / 128, 1), 256, GSM>>>(
        nullptr, 0, 0, wq, C_, 0, qkv, 3 * C_, 0, C_, qkv_b, x, nullptr,
        mean, rinv, sb);

    // 3: fused flash attention -> o [B, HW, C]
    flash_attn<<<dim3(HW_ / 128, B_), 256, FSM_TOT>>>(qkv, o);

    // 4: proj + residual + transpose, fused
    gemm_nt_bf16<true, false, true, false><<<dim3(C_ / 128, NTOK / 128, 1), 256, GSM>>>(
        o, C_, 0, wp, C_, 0, nullptr, C_, 0, C_, proj_b, x, out,
        nullptr, nullptr, nullptr);
}